// round 16
// baseline (speedup 1.0000x reference)
#include <cuda_runtime.h>
#include <cuda_bf16.h>
#include <math.h>
#include <stdint.h>

#define BB 2
#define LL 2048
#define DD 512
#define NHA 32
#define HDA 16
#define DIN 1024
#define NHM 16
#define PP 64
#define NNc 64
#define CONVD 1152
#define DPROJ 2192
#define EPSF 1e-5f
#define ROWS (BB*LL)

// ---------------- fp32 scratch ---------------------------------------------------
__device__ float g_qkv[ROWS * 3 * DD];
__device__ float g_aproj[2 * ROWS * DD];        // split-K partials
__device__ float g_h1[ROWS * DD];
__device__ float g_zx0[ROWS * DPROJ];
__device__ float g_zx1[ROWS * DPROJ];
__device__ float g_xbc0[ROWS * CONVD];
__device__ float g_xbc1[ROWS * CONVD];
__device__ float g_dt0[ROWS * NHM];
__device__ float g_dt1[ROWS * NHM];
__device__ float g_dA0[ROWS * NHM];
__device__ float g_dA1[ROWS * NHM];
__device__ float g_y0[ROWS * DIN];
__device__ float g_y1[ROWS * DIN];
__device__ float g_acc[2 * ROWS * DD];          // fwd out-proj partials
__device__ float g_acc2[2 * ROWS * DD];         // bwd out-proj partials

// ---------------- packed bf16 K/V for attention -----------------------------------
__device__ uint32_t g_kph[BB * NHA * LL * 8], g_kpl[BB * NHA * LL * 8];
__device__ uint32_t g_vph[BB * NHA * (LL/2) * 16], g_vpl[BB * NHA * (LL/2) * 16];

// ---------------- bf16 hi/lo split scratch ---------------------------------------
__device__ __nv_bfloat16 g_h_hi[ROWS * DD],  g_h_lo[ROWS * DD];
__device__ __nv_bfloat16 g_at_hi[ROWS * DD], g_at_lo[ROWS * DD];
__device__ __nv_bfloat16 g_h1_hi[ROWS * DD], g_h1_lo[ROWS * DD];
__device__ __nv_bfloat16 g_y0_hi[ROWS * DIN], g_y0_lo[ROWS * DIN];
__device__ __nv_bfloat16 g_y1_hi[ROWS * DIN], g_y1_lo[ROWS * DIN];
__device__ __nv_bfloat16 g_wqkv_hi[3 * DD * DD], g_wqkv_lo[3 * DD * DD];
__device__ __nv_bfloat16 g_woa_hi[DD * DD],      g_woa_lo[DD * DD];
__device__ __nv_bfloat16 g_fwi_hi[DPROJ * DD],   g_fwi_lo[DPROJ * DD];
__device__ __nv_bfloat16 g_bwi_hi[DPROJ * DD],   g_bwi_lo[DPROJ * DD];
__device__ __nv_bfloat16 g_fwo_hi[DD * DIN],     g_fwo_lo[DD * DIN];
__device__ __nv_bfloat16 g_bwo_hi[DD * DIN],     g_bwo_lo[DD * DIN];

// ---------------- helpers ---------------------------------------------------------
__device__ __forceinline__ void mma_bf16(float c[4],
                                         uint32_t a0, uint32_t a1, uint32_t a2, uint32_t a3,
                                         uint32_t b0, uint32_t b1)
{
    asm volatile(
        "mma.sync.aligned.m16n8k16.row.col.f32.bf16.bf16.f32 "
        "{%0,%1,%2,%3}, {%4,%5,%6,%7}, {%8,%9}, {%0,%1,%2,%3};"
        : "+f"(c[0]), "+f"(c[1]), "+f"(c[2]), "+f"(c[3])
        : "r"(a0), "r"(a1), "r"(a2), "r"(a3), "r"(b0), "r"(b1));
}

__device__ __forceinline__ void cp16(uint32_t dst, const void* src, bool p) {
    int sz = p ? 16 : 0;
    asm volatile("cp.async.cg.shared.global [%0], [%1], 16, %2;"
                 :: "r"(dst), "l"(src), "r"(sz));
}
__device__ __forceinline__ void cp_commit() {
    asm volatile("cp.async.commit_group;" ::: "memory");
}
__device__ __forceinline__ void cp_wait2() {
    asm volatile("cp.async.wait_group 2;" ::: "memory");
}

// pack two floats into bf16x2 hi word + bf16x2 residual-lo word (low half = first elem)
__device__ __forceinline__ void splitpack(float x, float y, uint32_t& hi, uint32_t& lo) {
    __nv_bfloat16 hx = __float2bfloat16(x), hy = __float2bfloat16(y);
    __nv_bfloat16 lx = __float2bfloat16(x - __bfloat162float(hx));
    __nv_bfloat16 ly = __float2bfloat16(y - __bfloat162float(hy));
    uint16_t uhx = *(uint16_t*)&hx, uhy = *(uint16_t*)&hy;
    uint16_t ulx = *(uint16_t*)&lx, uly = *(uint16_t*)&ly;
    hi = ((uint32_t)uhy << 16) | uhx;
    lo = ((uint32_t)uly << 16) | ulx;
}

// ---------------- segmented split (float4), all 7 fp32->bf16 splits ----------------
#define SP0 (3*DD*DD)
#define SP1 (SP0 + DD*DD)
#define SP2 (SP1 + DPROJ*DD)
#define SP3 (SP2 + DPROJ*DD)
#define SP4 (SP3 + DD*DIN)
#define SP5 (SP4 + DD*DIN)
#define SP6 (SP5 + ROWS*DD)
__global__ void split_all_kernel(
    const float* __restrict__ s0, __nv_bfloat16* __restrict__ h0, __nv_bfloat16* __restrict__ l0,
    const float* __restrict__ s1, __nv_bfloat16* __restrict__ h1, __nv_bfloat16* __restrict__ l1,
    const float* __restrict__ s2, __nv_bfloat16* __restrict__ h2, __nv_bfloat16* __restrict__ l2,
    const float* __restrict__ s3, __nv_bfloat16* __restrict__ h3, __nv_bfloat16* __restrict__ l3,
    const float* __restrict__ s4, __nv_bfloat16* __restrict__ h4, __nv_bfloat16* __restrict__ l4,
    const float* __restrict__ s5, __nv_bfloat16* __restrict__ h5, __nv_bfloat16* __restrict__ l5,
    const float* __restrict__ s6, __nv_bfloat16* __restrict__ h6, __nv_bfloat16* __restrict__ l6)
{
    int i4 = blockIdx.x * blockDim.x + threadIdx.x;
    if (i4 >= SP6 / 4) return;
    int i = i4 * 4;
    const float* src; __nv_bfloat16 *hi, *lo; int off;
    if (i < SP0)      { src = s0; hi = h0; lo = l0; off = i; }
    else if (i < SP1) { src = s1; hi = h1; lo = l1; off = i - SP0; }
    else if (i < SP2) { src = s2; hi = h2; lo = l2; off = i - SP1; }
    else if (i < SP3) { src = s3; hi = h3; lo = l3; off = i - SP2; }
    else if (i < SP4) { src = s4; hi = h4; lo = l4; off = i - SP3; }
    else if (i < SP5) { src = s5; hi = h5; lo = l5; off = i - SP4; }
    else              { src = s6; hi = h6; lo = l6; off = i - SP5; }
    float4 x = *(const float4*)(src + off);
    uint32_t ha, la, hb, lb;
    splitpack(x.x, x.y, ha, la);
    splitpack(x.z, x.w, hb, lb);
    *(uint2*)((char*)hi + off * 2) = make_uint2(ha, hb);
    *(uint2*)((char*)lo + off * 2) = make_uint2(la, lb);
}

// ---------------- pack K/V into attention tile layout (bf16 hi/lo) -----------------
// K: kp[(b*NHA+h)*LL + key][j] = pack(K[key][2j], K[key][2j+1]), j<8
// V: vp[(b*NHA+h)*(LL/2) + kp][hd] = pack(V[2kp][hd], V[2kp+1][hd]), hd<16
__global__ void pack_kv_kernel(const float* __restrict__ qkv,
                               uint32_t* __restrict__ kph, uint32_t* __restrict__ kpl,
                               uint32_t* __restrict__ vph, uint32_t* __restrict__ vpl)
{
    int tid = blockIdx.x * blockDim.x + threadIdx.x;
    if (tid >= BB * NHA * (LL / 2)) return;
    int h = tid & 31;
    int kp = (tid >> 5) & (LL / 2 - 1);
    int b = tid >> 15;
    const float* k0 = qkv + ((size_t)(b * LL + 2 * kp)) * 1536 + 512 + h * 16;
    const float* k1 = k0 + 1536;
    const float* v0 = k0 + 512;
    const float* v1 = v0 + 1536;
    size_t kb0 = ((size_t)(b * NHA + h) * LL + 2 * kp) * 8;
#pragma unroll
    for (int j = 0; j < 8; j++) {
        uint32_t hi, lo;
        splitpack(k0[2 * j], k0[2 * j + 1], hi, lo);
        kph[kb0 + j] = hi; kpl[kb0 + j] = lo;
        splitpack(k1[2 * j], k1[2 * j + 1], hi, lo);
        kph[kb0 + 8 + j] = hi; kpl[kb0 + 8 + j] = lo;
    }
    size_t vb = ((size_t)(b * NHA + h) * (LL / 2) + kp) * 16;
#pragma unroll
    for (int hd = 0; hd < 16; hd++) {
        uint32_t hi, lo;
        splitpack(v0[hd], v1[hd], hi, lo);
        vph[vb + hd] = hi; vpl[vb + hd] = lo;
    }
}

// ---------------- NT GEMM: bf16 3-product, 4-stage, dual-problem + split-K ---------
// blockIdx.z: prob = z / ksplit, kz = z % ksplit. Each kz computes K-range
// [kz*Kk/ksplit, ...) and writes partial C + kz*ROWS*Nn. bias/addsrc on kz==0 only.
#define ROWB 48
#define ATILE (128 * ROWB)
#define BTILE (64 * ROWB)
#define STAGE (2 * ATILE + 2 * BTILE)   // 18432
#define GSMEM (4 * STAGE)               // 73728
__global__ __launch_bounds__(256, 3) void gemm_nt(
    const __nv_bfloat16* __restrict__ Ahi0, const __nv_bfloat16* __restrict__ Alo0,
    const __nv_bfloat16* __restrict__ Whi0, const __nv_bfloat16* __restrict__ Wlo0,
    const float* __restrict__ bias0, const float* __restrict__ addsrc0,
    float* __restrict__ C0, int revA0, int revC0,
    const __nv_bfloat16* __restrict__ Ahi1, const __nv_bfloat16* __restrict__ Alo1,
    const __nv_bfloat16* __restrict__ Whi1, const __nv_bfloat16* __restrict__ Wlo1,
    const float* __restrict__ bias1, const float* __restrict__ addsrc1,
    float* __restrict__ C1, int revA1, int revC1,
    int Nn, int Kk, int ksplit)
{
    extern __shared__ char smem[];
    int prob = blockIdx.z / ksplit;
    int kz = blockIdx.z % ksplit;
    const __nv_bfloat16 *Ahi, *Alo, *Whi, *Wlo;
    const float *bias, *addsrc; float* C; int revA, revC;
    if (prob == 0) {
        Ahi = Ahi0; Alo = Alo0; Whi = Whi0; Wlo = Wlo0;
        bias = bias0; addsrc = addsrc0; C = C0; revA = revA0; revC = revC0;
    } else {
        Ahi = Ahi1; Alo = Alo1; Whi = Whi1; Wlo = Wlo1;
        bias = bias1; addsrc = addsrc1; C = C1; revA = revA1; revC = revC1;
    }
    int Keff = Kk / ksplit;
    int Koff = kz * Keff;
    C += (size_t)kz * ROWS * Nn;
    if (kz != 0) { bias = nullptr; addsrc = nullptr; }

    int t = threadIdx.x;
    int lane = t & 31, w = t >> 5;
    int wm = w & 3, wn = w >> 2;
    int m0 = blockIdx.y * 128;
    int n0 = blockIdx.x * 64;
    int g = lane >> 2, tg = lane & 3;
    int nk = Keff >> 4;

    int ar = t >> 1, ac16 = t & 1;
    int am = m0 + ar;
    if (revA) am = (am & ~2047) + (2047 - (am & 2047));
    const __nv_bfloat16* paH = Ahi + (size_t)am * Kk + Koff + ac16 * 8;
    const __nv_bfloat16* paL = Alo + (size_t)am * Kk + Koff + ac16 * 8;
    uint32_t a_off = ar * ROWB + ac16 * 16;

    int br = (t & 127) >> 1, bc16 = t & 1;
    bool bdo = (t < 128);
    bool bok = bdo && (n0 + br) < Nn;
    int bn = bok ? (n0 + br) : 0;
    const __nv_bfloat16* pbH = Whi + (size_t)bn * Kk + Koff + bc16 * 8;
    const __nv_bfloat16* pbL = Wlo + (size_t)bn * Kk + Koff + bc16 * 8;
    uint32_t b_off = br * ROWB + bc16 * 16;

    uint32_t sbase = (uint32_t)__cvta_generic_to_shared(smem);

    float acc[2][4][4];
#pragma unroll
    for (int mi = 0; mi < 2; mi++)
#pragma unroll
        for (int ni = 0; ni < 4; ni++)
#pragma unroll
            for (int e = 0; e < 4; e++) acc[mi][ni][e] = 0.f;

    auto load_slab = [&](int s, int stg) {
        uint32_t base = sbase + stg * STAGE;
        int k0 = s * 16;
        cp16(base + a_off, paH + k0, true);
        cp16(base + ATILE + a_off, paL + k0, true);
        if (bdo) {
            cp16(base + 2 * ATILE + b_off, pbH + k0, bok);
            cp16(base + 2 * ATILE + BTILE + b_off, pbL + k0, bok);
        }
    };

    load_slab(0, 0); cp_commit();
    load_slab(1, 1); cp_commit();
    load_slab(2, 2); cp_commit();

    for (int s = 0; s < nk; s++) {
        cp_wait2();
        __syncthreads();
        if (s + 3 < nk) load_slab(s + 3, (s + 3) & 3);
        cp_commit();
        const char* aH = smem + (s & 3) * STAGE;
        const char* aL = aH + ATILE;
        const char* bH = aH + 2 * ATILE;
        const char* bL = bH + BTILE;

        uint32_t ah[2][4], al[2][4];
#pragma unroll
        for (int mi = 0; mi < 2; mi++) {
            int r0 = wm * 32 + mi * 16 + g;
            ah[mi][0] = *(const uint32_t*)(aH + r0 * ROWB + tg * 4);
            ah[mi][1] = *(const uint32_t*)(aH + (r0 + 8) * ROWB + tg * 4);
            ah[mi][2] = *(const uint32_t*)(aH + r0 * ROWB + 16 + tg * 4);
            ah[mi][3] = *(const uint32_t*)(aH + (r0 + 8) * ROWB + 16 + tg * 4);
            al[mi][0] = *(const uint32_t*)(aL + r0 * ROWB + tg * 4);
            al[mi][1] = *(const uint32_t*)(aL + (r0 + 8) * ROWB + tg * 4);
            al[mi][2] = *(const uint32_t*)(aL + r0 * ROWB + 16 + tg * 4);
            al[mi][3] = *(const uint32_t*)(aL + (r0 + 8) * ROWB + 16 + tg * 4);
        }
        uint32_t bh[4][2], bl[4][2];
#pragma unroll
        for (int ni = 0; ni < 4; ni++) {
            int n = wn * 32 + ni * 8 + g;
            bh[ni][0] = *(const uint32_t*)(bH + n * ROWB + tg * 4);
            bh[ni][1] = *(const uint32_t*)(bH + n * ROWB + 16 + tg * 4);
            bl[ni][0] = *(const uint32_t*)(bL + n * ROWB + tg * 4);
            bl[ni][1] = *(const uint32_t*)(bL + n * ROWB + 16 + tg * 4);
        }
#pragma unroll
        for (int mi = 0; mi < 2; mi++)
#pragma unroll
            for (int ni = 0; ni < 4; ni++) {
                mma_bf16(acc[mi][ni], ah[mi][0], ah[mi][1], ah[mi][2], ah[mi][3],
                         bh[ni][0], bh[ni][1]);
                mma_bf16(acc[mi][ni], ah[mi][0], ah[mi][1], ah[mi][2], ah[mi][3],
                         bl[ni][0], bl[ni][1]);
                mma_bf16(acc[mi][ni], al[mi][0], al[mi][1], al[mi][2], al[mi][3],
                         bh[ni][0], bh[ni][1]);
            }
    }

#pragma unroll
    for (int mi = 0; mi < 2; mi++) {
#pragma unroll
        for (int ni = 0; ni < 4; ni++) {
            int row0 = m0 + wm * 32 + mi * 16 + g;
            int col0 = n0 + wn * 32 + ni * 8 + 2 * tg;
#pragma unroll
            for (int rr = 0; rr < 2; rr++) {
                int m = row0 + rr * 8;
                int mo = revC ? ((m & ~2047) + (2047 - (m & 2047))) : m;
#pragma unroll
                for (int cc = 0; cc < 2; cc++) {
                    int n = col0 + cc;
                    if (n >= Nn) continue;
                    float v = acc[mi][ni][rr * 2 + cc];
                    if (bias)   v += bias[n];
                    if (addsrc) v += addsrc[(size_t)m * Nn + n];
                    C[(size_t)mo * Nn + n] = v;
                }
            }
        }
    }
}

// ---------------- attention: bf16 mma 3-product flash, pre-packed K/V -------------
__global__ __launch_bounds__(256) void attn_kernel(const float* __restrict__ qkv,
                            const uint32_t* __restrict__ kph, const uint32_t* __restrict__ kpl,
                            const uint32_t* __restrict__ vphg, const uint32_t* __restrict__ vplg,
                            __nv_bfloat16* __restrict__ ohi,
                            __nv_bfloat16* __restrict__ olo)
{
    __shared__ uint32_t Kph[64][9], Kpl[64][9];
    __shared__ uint32_t Vph[32][16], Vpl[32][16];
    int b = blockIdx.z, h = blockIdx.y;
    int q0 = blockIdx.x * 128;
    int t = threadIdx.x, lane = t & 31, w = t >> 5;
    int g = lane >> 2, tg = lane & 3;
    int qrow0 = q0 + w * 16 + g;
    int qrow1 = qrow0 + 8;

    uint32_t aqh[4], aql[4];
    {
        const float* q0p = qkv + ((size_t)(b * LL + qrow0)) * 1536 + h * 16;
        const float* q1p = qkv + ((size_t)(b * LL + qrow1)) * 1536 + h * 16;
        splitpack(q0p[2*tg] * 0.25f,   q0p[2*tg+1] * 0.25f,   aqh[0], aql[0]);
        splitpack(q1p[2*tg] * 0.25f,   q1p[2*tg+1] * 0.25f,   aqh[1], aql[1]);
        splitpack(q0p[8+2*tg] * 0.25f, q0p[8+2*tg+1] * 0.25f, aqh[2], aql[2]);
        splitpack(q1p[8+2*tg] * 0.25f, q1p[8+2*tg+1] * 0.25f, aqh[3], aql[3]);
    }

    float m0 = -3.0e38f, m1 = -3.0e38f, l0 = 0.f, l1 = 0.f;
    float of[2][4];
#pragma unroll
    for (int n2 = 0; n2 < 2; n2++)
#pragma unroll
        for (int e = 0; e < 4; e++) of[n2][e] = 0.f;

    int skey = t >> 1, shalf = t & 1;
    int vu = t - 128, vkp = vu >> 2, vdg = vu & 3;
    size_t kbase = (size_t)(b * NHA + h) * LL * 8;
    size_t vbase = (size_t)(b * NHA + h) * (LL / 2) * 16;

    for (int j0 = 0; j0 < LL; j0 += 64) {
        __syncthreads();
        if (t < 128) {
            size_t off = kbase + (size_t)(j0 + skey) * 8 + shalf * 4;
            uint4 x = *(const uint4*)(kph + off);
            Kph[skey][shalf*4+0] = x.x; Kph[skey][shalf*4+1] = x.y;
            Kph[skey][shalf*4+2] = x.z; Kph[skey][shalf*4+3] = x.w;
            uint4 y = *(const uint4*)(kpl + off);
            Kpl[skey][shalf*4+0] = y.x; Kpl[skey][shalf*4+1] = y.y;
            Kpl[skey][shalf*4+2] = y.z; Kpl[skey][shalf*4+3] = y.w;
        } else {
            size_t off = vbase + (size_t)((j0 >> 1) + vkp) * 16 + vdg * 4;
            uint4 u = *(const uint4*)(vphg + off);
            Vph[vkp][vdg*4+0] = u.x; Vph[vkp][vdg*4+1] = u.y;
            Vph[vkp][vdg*4+2] = u.z; Vph[vkp][vdg*4+3] = u.w;
            uint4 v = *(const uint4*)(vplg + off);
            Vpl[vkp][vdg*4+0] = v.x; Vpl[vkp][vdg*4+1] = v.y;
            Vpl[vkp][vdg*4+2] = v.z; Vpl[vkp][vdg*4+3] = v.w;
        }
        __syncthreads();

        float sc[8][4];
#pragma unroll
        for (int nt = 0; nt < 8; nt++) {
            uint32_t bh0 = Kph[nt*8+g][tg],   bh1 = Kph[nt*8+g][4+tg];
            uint32_t bl0 = Kpl[nt*8+g][tg],   bl1 = Kpl[nt*8+g][4+tg];
            sc[nt][0] = sc[nt][1] = sc[nt][2] = sc[nt][3] = 0.f;
            mma_bf16(sc[nt], aqh[0], aqh[1], aqh[2], aqh[3], bh0, bh1);
            mma_bf16(sc[nt], aqh[0], aqh[1], aqh[2], aqh[3], bl0, bl1);
            mma_bf16(sc[nt], aql[0], aql[1], aql[2], aql[3], bh0, bh1);
        }

        float tm0 = -3.0e38f, tm1 = -3.0e38f;
#pragma unroll
        for (int nt = 0; nt < 8; nt++) {
            tm0 = fmaxf(tm0, fmaxf(sc[nt][0], sc[nt][1]));
            tm1 = fmaxf(tm1, fmaxf(sc[nt][2], sc[nt][3]));
        }
        tm0 = fmaxf(tm0, __shfl_xor_sync(0xffffffffu, tm0, 1));
        tm0 = fmaxf(tm0, __shfl_xor_sync(0xffffffffu, tm0, 2));
        tm1 = fmaxf(tm1, __shfl_xor_sync(0xffffffffu, tm1, 1));
        tm1 = fmaxf(tm1, __shfl_xor_sync(0xffffffffu, tm1, 2));
        float mn0 = fmaxf(m0, tm0), mn1 = fmaxf(m1, tm1);
        float al0 = __expf(m0 - mn0), al1 = __expf(m1 - mn1);
        m0 = mn0; m1 = mn1;
        l0 *= al0; l1 *= al1;
#pragma unroll
        for (int n2 = 0; n2 < 2; n2++) {
            of[n2][0] *= al0; of[n2][1] *= al0;
            of[n2][2] *= al1; of[n2][3] *= al1;
        }
        uint32_t PH0[8], PH1[8], PL0[8], PL1[8];
#pragma unroll
        for (int nt = 0; nt < 8; nt++) {
            float p0 = __expf(sc[nt][0] - m0), p1 = __expf(sc[nt][1] - m0);
            float p2 = __expf(sc[nt][2] - m1), p3 = __expf(sc[nt][3] - m1);
            l0 += p0 + p1; l1 += p2 + p3;
            splitpack(p0, p1, PH0[nt], PL0[nt]);
            splitpack(p2, p3, PH1[nt], PL1[nt]);
        }

#pragma unroll
        for (int ks = 0; ks < 4; ks++) {
#pragma unroll
            for (int n2 = 0; n2 < 2; n2++) {
                uint32_t b0h = Vph[8*ks+tg][n2*8+g],   b1h = Vph[8*ks+4+tg][n2*8+g];
                uint32_t b0l = Vpl[8*ks+tg][n2*8+g],   b1l = Vpl[8*ks+4+tg][n2*8+g];
                mma_bf16(of[n2], PH0[2*ks], PH1[2*ks], PH0[2*ks+1], PH1[2*ks+1], b0h, b1h);
                mma_bf16(of[n2], PH0[2*ks], PH1[2*ks], PH0[2*ks+1], PH1[2*ks+1], b0l, b1l);
                mma_bf16(of[n2], PL0[2*ks], PL1[2*ks], PL0[2*ks+1], PL1[2*ks+1], b0h, b1h);
            }
        }
    }

    l0 += __shfl_xor_sync(0xffffffffu, l0, 1);
    l0 += __shfl_xor_sync(0xffffffffu, l0, 2);
    l1 += __shfl_xor_sync(0xffffffffu, l1, 1);
    l1 += __shfl_xor_sync(0xffffffffu, l1, 2);
    float inv0 = 1.f / l0, inv1 = 1.f / l1;
    size_t o0 = ((size_t)(b * LL + qrow0)) * DD + h * 16;
    size_t o1 = ((size_t)(b * LL + qrow1)) * DD + h * 16;
#pragma unroll
    for (int n2 = 0; n2 < 2; n2++) {
#pragma unroll
        for (int e = 0; e < 2; e++) {
            int col = n2 * 8 + 2 * tg + e;
            float v0 = of[n2][e] * inv0;
            __nv_bfloat16 h0 = __float2bfloat16(v0);
            ohi[o0 + col] = h0;
            olo[o0 + col] = __float2bfloat16(v0 - __bfloat162float(h0));
            float v1 = of[n2][2 + e] * inv1;
            __nv_bfloat16 h1v = __float2bfloat16(v1);
            ohi[o1 + col] = h1v;
            olo[o1 + col] = __float2bfloat16(v1 - __bfloat162float(h1v));
        }
    }
}

// ---------------- layernorm (warp/row), float4, up to 3 add-sources ----------------
__global__ void ln_kernel(const float* __restrict__ X, const float* __restrict__ Y1,
                          const float* __restrict__ Y2, const float* __restrict__ Y3,
                          const float* __restrict__ g, const float* __restrict__ bb,
                          float* __restrict__ out,
                          __nv_bfloat16* __restrict__ ohi, __nv_bfloat16* __restrict__ olo)
{
    int warp = (blockIdx.x * blockDim.x + threadIdx.x) >> 5;
    int lane = threadIdx.x & 31;
    if (warp >= ROWS) return;
    const float4* x4 = (const float4*)(X + (size_t)warp * DD);
    const float4* y14 = Y1 ? (const float4*)(Y1 + (size_t)warp * DD) : nullptr;
    const float4* y24 = Y2 ? (const float4*)(Y2 + (size_t)warp * DD) : nullptr;
    const float4* y34 = Y3 ? (const float4*)(Y3 + (size_t)warp * DD) : nullptr;
    float4 v[4];
    float sum = 0.f;
#pragma unroll
    for (int i = 0; i < 4; i++) {
        int c4 = lane + i * 32;
        float4 tv = x4[c4];
        if (y14) { float4 a = y14[c4]; tv.x += a.x; tv.y += a.y; tv.z += a.z; tv.w += a.w; }
        if (y24) { float4 a = y24[c4]; tv.x += a.x; tv.y += a.y; tv.z += a.z; tv.w += a.w; }
        if (y34) { float4 a = y34[c4]; tv.x += a.x; tv.y += a.y; tv.z += a.z; tv.w += a.w; }
        v[i] = tv;
        sum += (tv.x + tv.y) + (tv.z + tv.w);
    }
#pragma unroll
    for (int o = 16; o > 0; o >>= 1) sum += __shfl_xor_sync(0xffffffffu, sum, o);
    float mean = sum * (1.f / DD);
    float vs = 0.f;
#pragma unroll
    for (int i = 0; i < 4; i++) {
        float dx = v[i].x - mean, dy = v[i].y - mean, dz = v[i].z - mean, dw = v[i].w - mean;
        vs += (dx*dx + dy*dy) + (dz*dz + dw*dw);
    }
#pragma unroll
    for (int o = 16; o > 0; o >>= 1) vs += __shfl_xor_sync(0xffffffffu, vs, o);
    float r = rsqrtf(vs * (1.f / DD) + EPSF);
    float4* op = (float4*)(out + (size_t)warp * DD);
    const float4* g4 = (const float4*)g;
    const float4* b4 = (const float4*)bb;
#pragma unroll
    for (int i = 0; i < 4; i++) {
        int c4 = lane + i * 32;
        float4 gv = g4[c4], bv = b4[c4];
        float4 ov;
        ov.x = (v[i].x - mean) * r * gv.x + bv.x;
        ov.y = (v[i].y - mean) * r * gv.y + bv.y;
        ov.z = (v[i].z - mean) * r * gv.z + bv.z;
        ov.w = (v[i].w - mean) * r * gv.w + bv.w;
        op[c4] = ov;
        if (ohi) {
            uint32_t ha, la, hb, lb;
            splitpack(ov.x, ov.y, ha, la);
            splitpack(ov.z, ov.w, hb, lb);
            ((uint2*)(ohi + (size_t)warp * DD))[c4] = make_uint2(ha, hb);
            ((uint2*)(olo + (size_t)warp * DD))[c4] = make_uint2(la, lb);
        }
    }
}

// ---------------- depthwise causal conv (K=4) + silu, 4 l/thread, both dirs -------
__global__ void conv_kernel(const float* __restrict__ zx0f, const float* __restrict__ cw0,
                            const float* __restrict__ cb0, float* __restrict__ xbc0f,
                            const float* __restrict__ zx1f, const float* __restrict__ cw1,
                            const float* __restrict__ cb1, float* __restrict__ xbc1f)
{
    int dir = blockIdx.y;
    const float* zx = dir ? zx1f : zx0f;
    const float* cw = dir ? cw1 : cw0;
    const float* cb = dir ? cb1 : cb0;
    float* xbc      = dir ? xbc1f : xbc0f;
    int tid = blockIdx.x * blockDim.x + threadIdx.x;
    if (tid >= (ROWS / 4) * CONVD) return;
    int c = tid % CONVD;
    int r4 = tid / CONVD;
    int bl0 = r4 * 4;
    int l0 = bl0 & 2047;
    const float* base = zx + (size_t)bl0 * DPROJ + DIN + c;
    float4 wv = *(const float4*)(cw + c * 4);
    float cbv = cb[c];
    float in[7];
#pragma unroll
    for (int j = 0; j < 7; j++) {
        int dl = j - 3;
        in[j] = (l0 + dl >= 0) ? base[dl * DPROJ] : 0.f;
    }
#pragma unroll
    for (int jo = 0; jo < 4; jo++) {
        float a = cbv;
        a = fmaf(in[jo],     wv.x, a);
        a = fmaf(in[jo + 1], wv.y, a);
        a = fmaf(in[jo + 2], wv.z, a);
        a = fmaf(in[jo + 3], wv.w, a);
        xbc[(size_t)(bl0 + jo) * CONVD + c] = a * (1.f / (1.f + __expf(-a)));
    }
}

// ---------------- dt / dA, both dirs ----------------------------------------------
__global__ void dtdA_kernel(const float* __restrict__ zx0f, const float* __restrict__ dtb0,
                            const float* __restrict__ Alog0,
                            float* __restrict__ dtf, float* __restrict__ dAf,
                            const float* __restrict__ zx1f, const float* __restrict__ dtb1,
                            const float* __restrict__ Alog1,
                            float* __restrict__ dtb_, float* __restrict__ dAb_)
{
    int dir = blockIdx.y;
    const float* zx  = dir ? zx1f : zx0f;
    const float* dtb = dir ? dtb1 : dtb0;
    const float* Alog= dir ? Alog1 : Alog0;
    float* dt = dir ? dtb_ : dtf;
    float* dA = dir ? dAb_ : dAf;
    int idx = blockIdx.x * blockDim.x + threadIdx.x;
    if (idx >= ROWS * NHM) return;
    int hm = idx & 15;
    int bl = idx >> 4;
    float raw = zx[(size_t)bl * DPROJ + (DPROJ - NHM) + hm] + dtb[hm];
    float dtv = (raw > 20.f) ? raw : log1pf(__expf(raw));
    float dAv = __expf(-__expf(Alog[hm]) * dtv);
    dt[idx] = dtv; dA[idx] = dAv;
}

// ---------------- sequential SSM scan: 2 steps per barrier, 4-buffer ring ---------
__global__ void scan_kernel(
    const float* __restrict__ xbc0, const float* __restrict__ dt0, const float* __restrict__ dA0,
    const float* __restrict__ Dp0, float* __restrict__ y0,
    const float* __restrict__ xbc1, const float* __restrict__ dt1, const float* __restrict__ dA1,
    const float* __restrict__ Dp1, float* __restrict__ y1)
{
    int z = blockIdx.z;
    int b = z & 1, dir = z >> 1;
    const float* xbc = dir ? xbc1 : xbc0;
    const float* dtp = dir ? dt1 : dt0;
    const float* dAp = dir ? dA1 : dA0;
    const float* Dp  = dir ? Dp1 : Dp0;
    float* y         = dir ? y1 : y0;
    int h = blockIdx.y, pc = blockIdx.x;
    int t = threadIdx.x;
    int p_local = t >> 1, nhalf = t & 1;

    __shared__ float sm[4][160];

    const float* src = nullptr;
    int stride = 0;
    if (t < 16)        { src = xbc + h * 64 + pc * 16 + t;      stride = CONVD; }
    else if (t < 80)   { src = xbc + DIN + (t - 16);            stride = CONVD; }
    else if (t < 144)  { src = xbc + DIN + NNc + (t - 80);      stride = CONVD; }
    else if (t == 144) { src = dtp + h;                         stride = NHM; }
    else if (t == 145) { src = dAp + h;                         stride = NHM; }

    size_t base_bl = (size_t)b * LL;
    if (src) src += base_bl * stride;

    float s[32];
#pragma unroll
    for (int k = 0; k < 32; k++) s[k] = 0.f;
    float dcoef = Dp[h];

    float r0 = 0.f, r1 = 0.f, r2 = 0.f, r3 = 0.f;
    if (src) {
        r0 = src[0];
        r1 = src[stride];
        r2 = src[2 * (size_t)stride];
        r3 = src[3 * (size_t)stride];
    }

    int pair = 0;
    for (int l = 0; l < LL; l += 2) {
        float* b0 = sm[2 * pair];
        float* b1 = sm[2 * pair + 1];
        if (t < 146) { b0[t] = r0; b1[t] = r1; }
        __syncthreads();
        r0 = r2; r1 = r3;
        if (src) {
            r2 = (l + 4 < LL) ? src[(size_t)(l + 4) * stride] : 0.f;
            r3 = (l + 5 < LL) ? src[(size_t)(l + 5) * stride] : 0.f;
        }
        if (t < 32) {
#pragma unroll
            for (int step = 0; step < 2; step++) {
                const float* bf = step ? b1 : b0;
                float dtv = bf[144];
                float dAv = bf[145];
                float xv  = bf[p_local];
                float cx  = dtv * xv;
                const float* Bb = bf + 16 + nhalf * 32;
                const float* Cb = bf + 80 + nhalf * 32;
                float pk[8];
#pragma unroll
                for (int k = 0; k < 8; k++) {
                    float4 Bv = *(const float4*)(Bb + 4 * k);
                    float4 Cv = *(const float4*)(Cb + 4 * k);
                    s[4*k+0] = fmaf(s[4*k+0], dAv, cx * Bv.x);
                    s[4*k+1] = fmaf(s[4*k+1], dAv, cx * Bv.y);
                    s[4*k+2] = fmaf(s[4*k+2], dAv, cx * Bv.z);
                    s[4*k+3] = fmaf(s[4*k+3], dAv, cx * Bv.w);
                    pk[k] = (s[4*k+0] * Cv.x + s[4*k+1] * Cv.y)
                          + (s[4*k+2] * Cv.z + s[4*k+3] * Cv.w);
                }
                float part = ((pk[0] + pk[1]) + (pk[2] + pk[3]))
                           + ((pk[4] + pk[5]) + (pk[6] + pk[7]));
                part += __shfl_xor_sync(0xffffffffu, part, 1);
                if (nhalf == 0)
                    y[(base_bl + l + step) * DIN + h * 64 + pc * 16 + p_local]
                        = part + dcoef * xv;
            }
        }
        pair ^= 1;
    }
}

// ---------------- gated RMSNorm, float4, fused bf16 split, both dirs --------------
__global__ void rmsgate_kernel(const float* __restrict__ y0f, const float* __restrict__ zx0f,
                               const float* __restrict__ nw0,
                               __nv_bfloat16* __restrict__ oh0, __nv_bfloat16* __restrict__ ol0,
                               const float* __restrict__ y1f, const float* __restrict__ zx1f,
                               const float* __restrict__ nw1,
                               __nv_bfloat16* __restrict__ oh1, __nv_bfloat16* __restrict__ ol1)
{
    int dir = blockIdx.y;
    const float* y  = dir ? y1f : y0f;
    const float* zx = dir ? zx1f : zx0f;
    const float* nw = dir ? nw1 : nw0;
    __nv_bfloat16* ohi = dir ? oh1 : oh0;
    __nv_bfloat16* olo = dir ? ol1 : ol0;
    int warp = (blockIdx.x * blockDim.x + threadIdx.x) >> 5;
    int lane = threadIdx.x & 31;
    if (warp >= ROWS) return;
    const float4* z4 = (const float4*)(zx + (size_t)warp * DPROJ);
    const float4* yr4 = (const float4*)(y + (size_t)warp * DIN);
    float4 v[8];
    float ss = 0.f;
#pragma unroll
    for (int i = 0; i < 8; i++) {
        int c4 = lane + i * 32;
        float4 zv = z4[c4];
        float4 yv = yr4[c4];
        yv.x *= zv.x * (1.f / (1.f + __expf(-zv.x)));
        yv.y *= zv.y * (1.f / (1.f + __expf(-zv.y)));
        yv.z *= zv.z * (1.f / (1.f + __expf(-zv.z)));
        yv.w *= zv.w * (1.f / (1.f + __expf(-zv.w)));
        v[i] = yv;
        ss += (yv.x*yv.x + yv.y*yv.y) + (yv.z*yv.z + yv.w*yv.w);
    }
#pragma unroll
    for (int o = 16; o > 0; o >>= 1) ss += __shfl_xor_sync(0xffffffffu, ss, o);
    float r = rsqrtf(ss * (1.f / DIN) + EPSF);
    const float4* nw4 = (const float4*)nw;
#pragma unroll
    for (int i = 0; i < 8; i++) {
        int c4 = lane + i * 32;
        float4 nv = nw4[c4];
        float a = v[i].x * r * nv.x, bq = v[i].y * r * nv.y;
        float cq = v[i].z * r * nv.z, d = v[i].w * r * nv.w;
        uint32_t ha, la, hb, lb;
        splitpack(a, bq, ha, la);
        splitpack(cq, d, hb, lb);
        ((uint2*)(ohi + (size_t)warp * DIN))[c4] = make_uint2(ha, hb);
        ((uint2*)(olo + (size_t)warp * DIN))[c4] = make_uint2(la, lb);
    }
}

// ---------------- launcher ---------------------------------------------------------
extern "C" void kernel_launch(void* const* d_in, const int* in_sizes, int n_in,
                              void* d_out, int out_size)
{
    const float* h      = (const float*)d_in[0];
    const float* Wqkv   = (const float*)d_in[1];
    const float* bqkv   = (const float*)d_in[2];
    const float* Wo_a   = (const float*)d_in[3];
    const float* bo_a   = (const float*)d_in[4];
    const float* g1     = (const float*)d_in[5];
    const float* b1     = (const float*)d_in[6];
    const float* g2     = (const float*)d_in[7];
    const float* b2     = (const float*)d_in[8];
    const float* f_Wi   = (const float*)d_in[9];
    const float* f_cw   = (const float*)d_in[10];
    const float* f_cb   = (const float*)d_in[11];
    const float* f_dtb  = (const float*)d_in[12];
    const float* f_Alog = (const float*)d_in[13];
    const float* f_D    = (const float*)d_in[14];
    const float* f_nw   = (const float*)d_in[15];
    const float* f_Wo   = (const float*)d_in[16];
    const float* bw_Wi  = (const float*)d_in[17];
    const float* bw_cw  = (const float*)d_in[18];
    const float* bw_cb  = (const float*)d_in[19];
    const float* bw_dtb = (const float*)d_in[20];
    const float* bw_Alog= (const float*)d_in[21];
    const float* bw_D   = (const float*)d_in[22];
    const float* bw_nw  = (const float*)d_in[23];
    const float* bw_Wo  = (const float*)d_in[24];
    float* out = (float*)d_out;

    cudaFuncSetAttribute(gemm_nt, cudaFuncAttributeMaxDynamicSharedMemorySize, GSMEM);

    float *qkvb, *aproj, *h1, *zx0, *zx1, *xbc0, *xbc1;
    float *dt0, *dt1, *dA0, *dA1, *y0, *y1, *acc, *acc2;
    cudaGetSymbolAddress((void**)&qkvb, g_qkv);
    cudaGetSymbolAddress((void**)&aproj, g_aproj);
    cudaGetSymbolAddress((void**)&h1, g_h1);
    cudaGetSymbolAddress((void**)&zx0, g_zx0);
    cudaGetSymbolAddress((void**)&zx1, g_zx1);
    cudaGetSymbolAddress((void**)&xbc0, g_xbc0);
    cudaGetSymbolAddress((void**)&xbc1, g_xbc1);
    cudaGetSymbolAddress((void**)&dt0, g_dt0);
    cudaGetSymbolAddress((void**)&dt1, g_dt1);
    cudaGetSymbolAddress((void**)&dA0, g_dA0);
    cudaGetSymbolAddress((void**)&dA1, g_dA1);
    cudaGetSymbolAddress((void**)&y0, g_y0);
    cudaGetSymbolAddress((void**)&y1, g_y1);
    cudaGetSymbolAddress((void**)&acc, g_acc);
    cudaGetSymbolAddress((void**)&acc2, g_acc2);

    uint32_t *kph, *kpl, *vph, *vpl;
    cudaGetSymbolAddress((void**)&kph, g_kph);
    cudaGetSymbolAddress((void**)&kpl, g_kpl);
    cudaGetSymbolAddress((void**)&vph, g_vph);
    cudaGetSymbolAddress((void**)&vpl, g_vpl);

    __nv_bfloat16 *hH, *hL, *atH, *atL, *h1H, *h1L, *y0H, *y0L, *y1H, *y1L;
    __nv_bfloat16 *wqH, *wqL, *waH, *waL, *fiH, *fiL, *biH, *biL, *foH, *foL, *boH, *boL;
    cudaGetSymbolAddress((void**)&hH, g_h_hi);   cudaGetSymbolAddress((void**)&hL, g_h_lo);
    cudaGetSymbolAddress((void**)&atH, g_at_hi); cudaGetSymbolAddress((void**)&atL, g_at_lo);
    cudaGetSymbolAddress((void**)&h1H, g_h1_hi); cudaGetSymbolAddress((void**)&h1L, g_h1_lo);
    cudaGetSymbolAddress((void**)&y0H, g_y0_hi); cudaGetSymbolAddress((void**)&y0L, g_y0_lo);
    cudaGetSymbolAddress((void**)&y1H, g_y1_hi); cudaGetSymbolAddress((void**)&y1L, g_y1_lo);
    cudaGetSymbolAddress((void**)&wqH, g_wqkv_hi); cudaGetSymbolAddress((void**)&wqL, g_wqkv_lo);
    cudaGetSymbolAddress((void**)&waH, g_woa_hi);  cudaGetSymbolAddress((void**)&waL, g_woa_lo);
    cudaGetSymbolAddress((void**)&fiH, g_fwi_hi);  cudaGetSymbolAddress((void**)&fiL, g_fwi_lo);
    cudaGetSymbolAddress((void**)&biH, g_bwi_hi);  cudaGetSymbolAddress((void**)&biL, g_bwi_lo);
    cudaGetSymbolAddress((void**)&foH, g_fwo_hi);  cudaGetSymbolAddress((void**)&foL, g_fwo_lo);
    cudaGetSymbolAddress((void**)&boH, g_bwo_hi);  cudaGetSymbolAddress((void**)&boL, g_bwo_lo);

    // 0) one segmented float4 split for all weights + h
    split_all_kernel<<<(SP6 / 4 + 255) / 256, 256>>>(
        Wqkv, wqH, wqL,  Wo_a, waH, waL,  f_Wi, fiH, fiL,  bw_Wi, biH, biL,
        f_Wo, foH, foL,  bw_Wo, boH, boL,  h, hH, hL);

    // 1) qkv = h @ Wqkv^T + bqkv (single problem, no split)
    gemm_nt<<<dim3(24, 32, 1), 256, GSMEM>>>(
        hH, hL, wqH, wqL, bqkv, nullptr, qkvb, 0, 0,
        hH, hL, wqH, wqL, bqkv, nullptr, qkvb, 0, 0,
        1536, 512, 1);
    // 1b) pack K/V into bf16 tile layout
    pack_kv_kernel<<<(BB * NHA * (LL/2) + 255) / 256, 256>>>(qkvb, kph, kpl, vph, vpl);
    // 2) attention (pre-packed K/V)
    attn_kernel<<<dim3(16, 32, 2), 256>>>(qkvb, kph, kpl, vph, vpl, atH, atL);
    // 3) attn out-proj, split-K=2 (z=2, prob 0)
    gemm_nt<<<dim3(8, 32, 2), 256, GSMEM>>>(
        atH, atL, waH, waL, bo_a, nullptr, aproj, 0, 0,
        atH, atL, waH, waL, bo_a, nullptr, aproj, 0, 0,
        512, 512, 2);
    // 4) h1 = LN(h + aproj_k0 + aproj_k1), fused split
    ln_kernel<<<512, 256>>>(h, aproj, aproj + (size_t)ROWS * DD, nullptr,
                            g1, b1, h1, h1H, h1L);
    // 5) mamba in-projections fwd+bwd merged (z=2, no split)
    gemm_nt<<<dim3(35, 32, 2), 256, GSMEM>>>(
        h1H, h1L, fiH, fiL, nullptr, nullptr, zx0, 0, 0,
        h1H, h1L, biH, biL, nullptr, nullptr, zx1, 1, 0,
        DPROJ, 512, 1);
    // 6) depthwise conv + silu (4 l/thread, both dirs)
    conv_kernel<<<dim3(((ROWS / 4) * CONVD + 255) / 256, 2), 256>>>(
        zx0, f_cw, f_cb, xbc0, zx1, bw_cw, bw_cb, xbc1);
    // 7) dt / dA (both dirs)
    dtdA_kernel<<<dim3(256, 2), 256>>>(zx0, f_dtb, f_Alog, dt0, dA0,
                                       zx1, bw_dtb, bw_Alog, dt1, dA1);
    // 8) SSM scan, both directions concurrently (2 steps/barrier)
    scan_kernel<<<dim3(4, 16, 4), 160>>>(xbc0, dt0, dA0, f_D, y0,
                                         xbc1, dt1, dA1, bw_D, y1);
    // 9) gated RMSNorm, fused split (both dirs)
    rmsgate_kernel<<<dim3(512, 2), 256>>>(y0, zx0, f_nw, y0H, y0L,
                                          y1, zx1, bw_nw, y1H, y1L);
    // 10) out-projections merged + split-K=2 (z=4):
    //     prob0: acc[k] = (h1 on k0) + partial(yf@fWo^T); prob1: acc2[k] = rev partials
    gemm_nt<<<dim3(8, 32, 4), 256, GSMEM>>>(
        y0H, y0L, foH, foL, nullptr, h1, acc, 0, 0,
        y1H, y1L, boH, boL, nullptr, nullptr, acc2, 0, 1,
        512, 1024, 2);
    // 11) final LN over (acc_k0 + acc_k1 + acc2_k0 + acc2_k1)
    ln_kernel<<<512, 256>>>(acc, acc + (size_t)ROWS * DD, acc2, acc2 + (size_t)ROWS * DD,
                            g2, b2, out, nullptr, nullptr);
}

// round 17
// speedup vs baseline: 1.6825x; 1.6825x over previous
#include <cuda_runtime.h>
#include <cuda_bf16.h>
#include <math.h>
#include <stdint.h>

#define BB 2
#define LL 2048
#define DD 512
#define NHA 32
#define HDA 16
#define DIN 1024
#define NHM 16
#define PP 64
#define NNc 64
#define CONVD 1152
#define DPROJ 2192
#define EPSF 1e-5f
#define ROWS (BB*LL)

// ---------------- fp32 scratch ---------------------------------------------------
__device__ float g_qkv[ROWS * 3 * DD];
__device__ float g_aproj[ROWS * DD];
__device__ float g_h1[ROWS * DD];
__device__ float g_zx0[ROWS * DPROJ];
__device__ float g_zx1[ROWS * DPROJ];
__device__ float g_xbc0[ROWS * CONVD];
__device__ float g_xbc1[ROWS * CONVD];
__device__ float g_dt0[ROWS * NHM];
__device__ float g_dt1[ROWS * NHM];
__device__ float g_dA0[ROWS * NHM];
__device__ float g_dA1[ROWS * NHM];
__device__ float g_y0[ROWS * DIN];
__device__ float g_y1[ROWS * DIN];
__device__ float g_acc[ROWS * DD];
__device__ float g_acc2[ROWS * DD];

// ---------------- bf16 hi/lo split scratch ---------------------------------------
__device__ __nv_bfloat16 g_h_hi[ROWS * DD],  g_h_lo[ROWS * DD];
__device__ __nv_bfloat16 g_at_hi[ROWS * DD], g_at_lo[ROWS * DD];
__device__ __nv_bfloat16 g_h1_hi[ROWS * DD], g_h1_lo[ROWS * DD];
__device__ __nv_bfloat16 g_y0_hi[ROWS * DIN], g_y0_lo[ROWS * DIN];
__device__ __nv_bfloat16 g_y1_hi[ROWS * DIN], g_y1_lo[ROWS * DIN];
__device__ __nv_bfloat16 g_wqkv_hi[3 * DD * DD], g_wqkv_lo[3 * DD * DD];
__device__ __nv_bfloat16 g_woa_hi[DD * DD],      g_woa_lo[DD * DD];
__device__ __nv_bfloat16 g_fwi_hi[DPROJ * DD],   g_fwi_lo[DPROJ * DD];
__device__ __nv_bfloat16 g_bwi_hi[DPROJ * DD],   g_bwi_lo[DPROJ * DD];
__device__ __nv_bfloat16 g_fwo_hi[DD * DIN],     g_fwo_lo[DD * DIN];
__device__ __nv_bfloat16 g_bwo_hi[DD * DIN],     g_bwo_lo[DD * DIN];

// ---------------- helpers ---------------------------------------------------------
__device__ __forceinline__ void mma_bf16(float c[4],
                                         uint32_t a0, uint32_t a1, uint32_t a2, uint32_t a3,
                                         uint32_t b0, uint32_t b1)
{
    asm volatile(
        "mma.sync.aligned.m16n8k16.row.col.f32.bf16.bf16.f32 "
        "{%0,%1,%2,%3}, {%4,%5,%6,%7}, {%8,%9}, {%0,%1,%2,%3};"
        : "+f"(c[0]), "+f"(c[1]), "+f"(c[2]), "+f"(c[3])
        : "r"(a0), "r"(a1), "r"(a2), "r"(a3), "r"(b0), "r"(b1));
}

__device__ __forceinline__ void cp16(uint32_t dst, const void* src, bool p) {
    int sz = p ? 16 : 0;
    asm volatile("cp.async.cg.shared.global [%0], [%1], 16, %2;"
                 :: "r"(dst), "l"(src), "r"(sz));
}
__device__ __forceinline__ void cp_commit() {
    asm volatile("cp.async.commit_group;" ::: "memory");
}
__device__ __forceinline__ void cp_wait2() {
    asm volatile("cp.async.wait_group 2;" ::: "memory");
}

// pack two floats into bf16x2 hi word + bf16x2 residual-lo word (low half = first elem)
__device__ __forceinline__ void splitpack(float x, float y, uint32_t& hi, uint32_t& lo) {
    __nv_bfloat16 hx = __float2bfloat16(x), hy = __float2bfloat16(y);
    __nv_bfloat16 lx = __float2bfloat16(x - __bfloat162float(hx));
    __nv_bfloat16 ly = __float2bfloat16(y - __bfloat162float(hy));
    uint16_t uhx = *(uint16_t*)&hx, uhy = *(uint16_t*)&hy;
    uint16_t ulx = *(uint16_t*)&lx, uly = *(uint16_t*)&ly;
    hi = ((uint32_t)uhy << 16) | uhx;
    lo = ((uint32_t)uly << 16) | ulx;
}

// pack two floats into a single bf16x2 word (round-to-nearest)
__device__ __forceinline__ uint32_t pack2bf(float x, float y) {
    __nv_bfloat162 t = __floats2bfloat162_rn(x, y);
    return *(uint32_t*)&t;
}

// ---------------- segmented split (float4), all 7 fp32->bf16 splits ----------------
#define SP0 (3*DD*DD)
#define SP1 (SP0 + DD*DD)
#define SP2 (SP1 + DPROJ*DD)
#define SP3 (SP2 + DPROJ*DD)
#define SP4 (SP3 + DD*DIN)
#define SP5 (SP4 + DD*DIN)
#define SP6 (SP5 + ROWS*DD)
__global__ void split_all_kernel(
    const float* __restrict__ s0, __nv_bfloat16* __restrict__ h0, __nv_bfloat16* __restrict__ l0,
    const float* __restrict__ s1, __nv_bfloat16* __restrict__ h1, __nv_bfloat16* __restrict__ l1,
    const float* __restrict__ s2, __nv_bfloat16* __restrict__ h2, __nv_bfloat16* __restrict__ l2,
    const float* __restrict__ s3, __nv_bfloat16* __restrict__ h3, __nv_bfloat16* __restrict__ l3,
    const float* __restrict__ s4, __nv_bfloat16* __restrict__ h4, __nv_bfloat16* __restrict__ l4,
    const float* __restrict__ s5, __nv_bfloat16* __restrict__ h5, __nv_bfloat16* __restrict__ l5,
    const float* __restrict__ s6, __nv_bfloat16* __restrict__ h6, __nv_bfloat16* __restrict__ l6)
{
    int i4 = blockIdx.x * blockDim.x + threadIdx.x;
    if (i4 >= SP6 / 4) return;
    int i = i4 * 4;
    const float* src; __nv_bfloat16 *hi, *lo; int off;
    if (i < SP0)      { src = s0; hi = h0; lo = l0; off = i; }
    else if (i < SP1) { src = s1; hi = h1; lo = l1; off = i - SP0; }
    else if (i < SP2) { src = s2; hi = h2; lo = l2; off = i - SP1; }
    else if (i < SP3) { src = s3; hi = h3; lo = l3; off = i - SP2; }
    else if (i < SP4) { src = s4; hi = h4; lo = l4; off = i - SP3; }
    else if (i < SP5) { src = s5; hi = h5; lo = l5; off = i - SP4; }
    else              { src = s6; hi = h6; lo = l6; off = i - SP5; }
    float4 x = *(const float4*)(src + off);
    uint32_t ha, la, hb, lb;
    splitpack(x.x, x.y, ha, la);
    splitpack(x.z, x.w, hb, lb);
    *(uint2*)((char*)hi + off * 2) = make_uint2(ha, hb);
    *(uint2*)((char*)lo + off * 2) = make_uint2(la, lb);
}

// ---------------- NT GEMM: bf16 3-product mma.sync, 4-stage, dist-3 prefetch ------
#define ROWB 48
#define ATILE (128 * ROWB)
#define BTILE (64 * ROWB)
#define STAGE (2 * ATILE + 2 * BTILE)   // 18432
#define GSMEM (4 * STAGE)               // 73728
__global__ __launch_bounds__(256, 3) void gemm_nt(
    const __nv_bfloat16* __restrict__ Ahi0, const __nv_bfloat16* __restrict__ Alo0,
    const __nv_bfloat16* __restrict__ Whi0, const __nv_bfloat16* __restrict__ Wlo0,
    const float* __restrict__ bias0, const float* __restrict__ addsrc0,
    float* __restrict__ C0, int revA0, int revC0,
    const __nv_bfloat16* __restrict__ Ahi1, const __nv_bfloat16* __restrict__ Alo1,
    const __nv_bfloat16* __restrict__ Whi1, const __nv_bfloat16* __restrict__ Wlo1,
    const float* __restrict__ bias1, const float* __restrict__ addsrc1,
    float* __restrict__ C1, int revA1, int revC1,
    int Nn, int Kk)
{
    extern __shared__ char smem[];
    const __nv_bfloat16 *Ahi, *Alo, *Whi, *Wlo;
    const float *bias, *addsrc; float* C; int revA, revC;
    if (blockIdx.z == 0) {
        Ahi = Ahi0; Alo = Alo0; Whi = Whi0; Wlo = Wlo0;
        bias = bias0; addsrc = addsrc0; C = C0; revA = revA0; revC = revC0;
    } else {
        Ahi = Ahi1; Alo = Alo1; Whi = Whi1; Wlo = Wlo1;
        bias = bias1; addsrc = addsrc1; C = C1; revA = revA1; revC = revC1;
    }

    int t = threadIdx.x;
    int lane = t & 31, w = t >> 5;
    int wm = w & 3, wn = w >> 2;
    int m0 = blockIdx.y * 128;
    int n0 = blockIdx.x * 64;
    int g = lane >> 2, tg = lane & 3;
    int nk = Kk >> 4;

    int ar = t >> 1, ac16 = t & 1;
    int am = m0 + ar;
    if (revA) am = (am & ~2047) + (2047 - (am & 2047));
    const __nv_bfloat16* paH = Ahi + (size_t)am * Kk + ac16 * 8;
    const __nv_bfloat16* paL = Alo + (size_t)am * Kk + ac16 * 8;
    uint32_t a_off = ar * ROWB + ac16 * 16;

    int br = (t & 127) >> 1, bc16 = t & 1;
    bool bdo = (t < 128);
    bool bok = bdo && (n0 + br) < Nn;
    int bn = bok ? (n0 + br) : 0;
    const __nv_bfloat16* pbH = Whi + (size_t)bn * Kk + bc16 * 8;
    const __nv_bfloat16* pbL = Wlo + (size_t)bn * Kk + bc16 * 8;
    uint32_t b_off = br * ROWB + bc16 * 16;

    uint32_t sbase = (uint32_t)__cvta_generic_to_shared(smem);

    float acc[2][4][4];
#pragma unroll
    for (int mi = 0; mi < 2; mi++)
#pragma unroll
        for (int ni = 0; ni < 4; ni++)
#pragma unroll
            for (int e = 0; e < 4; e++) acc[mi][ni][e] = 0.f;

    auto load_slab = [&](int s, int stg) {
        uint32_t base = sbase + stg * STAGE;
        int k0 = s * 16;
        cp16(base + a_off, paH + k0, true);
        cp16(base + ATILE + a_off, paL + k0, true);
        if (bdo) {
            cp16(base + 2 * ATILE + b_off, pbH + k0, bok);
            cp16(base + 2 * ATILE + BTILE + b_off, pbL + k0, bok);
        }
    };

    load_slab(0, 0); cp_commit();
    load_slab(1, 1); cp_commit();
    load_slab(2, 2); cp_commit();

    for (int s = 0; s < nk; s++) {
        cp_wait2();
        __syncthreads();
        if (s + 3 < nk) load_slab(s + 3, (s + 3) & 3);
        cp_commit();
        const char* aH = smem + (s & 3) * STAGE;
        const char* aL = aH + ATILE;
        const char* bH = aH + 2 * ATILE;
        const char* bL = bH + BTILE;

        uint32_t ah[2][4], al[2][4];
#pragma unroll
        for (int mi = 0; mi < 2; mi++) {
            int r0 = wm * 32 + mi * 16 + g;
            ah[mi][0] = *(const uint32_t*)(aH + r0 * ROWB + tg * 4);
            ah[mi][1] = *(const uint32_t*)(aH + (r0 + 8) * ROWB + tg * 4);
            ah[mi][2] = *(const uint32_t*)(aH + r0 * ROWB + 16 + tg * 4);
            ah[mi][3] = *(const uint32_t*)(aH + (r0 + 8) * ROWB + 16 + tg * 4);
            al[mi][0] = *(const uint32_t*)(aL + r0 * ROWB + tg * 4);
            al[mi][1] = *(const uint32_t*)(aL + (r0 + 8) * ROWB + tg * 4);
            al[mi][2] = *(const uint32_t*)(aL + r0 * ROWB + 16 + tg * 4);
            al[mi][3] = *(const uint32_t*)(aL + (r0 + 8) * ROWB + 16 + tg * 4);
        }
        uint32_t bh[4][2], bl[4][2];
#pragma unroll
        for (int ni = 0; ni < 4; ni++) {
            int n = wn * 32 + ni * 8 + g;
            bh[ni][0] = *(const uint32_t*)(bH + n * ROWB + tg * 4);
            bh[ni][1] = *(const uint32_t*)(bH + n * ROWB + 16 + tg * 4);
            bl[ni][0] = *(const uint32_t*)(bL + n * ROWB + tg * 4);
            bl[ni][1] = *(const uint32_t*)(bL + n * ROWB + 16 + tg * 4);
        }
#pragma unroll
        for (int mi = 0; mi < 2; mi++)
#pragma unroll
            for (int ni = 0; ni < 4; ni++) {
                mma_bf16(acc[mi][ni], ah[mi][0], ah[mi][1], ah[mi][2], ah[mi][3],
                         bh[ni][0], bh[ni][1]);
                mma_bf16(acc[mi][ni], ah[mi][0], ah[mi][1], ah[mi][2], ah[mi][3],
                         bl[ni][0], bl[ni][1]);
                mma_bf16(acc[mi][ni], al[mi][0], al[mi][1], al[mi][2], al[mi][3],
                         bh[ni][0], bh[ni][1]);
            }
    }

#pragma unroll
    for (int mi = 0; mi < 2; mi++) {
#pragma unroll
        for (int ni = 0; ni < 4; ni++) {
            int row0 = m0 + wm * 32 + mi * 16 + g;
            int col0 = n0 + wn * 32 + ni * 8 + 2 * tg;
#pragma unroll
            for (int rr = 0; rr < 2; rr++) {
                int m = row0 + rr * 8;
                int mo = revC ? ((m & ~2047) + (2047 - (m & 2047))) : m;
#pragma unroll
                for (int cc = 0; cc < 2; cc++) {
                    int n = col0 + cc;
                    if (n >= Nn) continue;
                    float v = acc[mi][ni][rr * 2 + cc];
                    if (bias)   v += bias[n];
                    if (addsrc) v += addsrc[(size_t)m * Nn + n];
                    C[(size_t)mo * Nn + n] = v;
                }
            }
        }
    }
}

// ---------------- attention: bf16 mma flash, P in bf16 (2-product PV) -------------
__global__ __launch_bounds__(256) void attn_kernel(const float* __restrict__ qkv,
                            __nv_bfloat16* __restrict__ ohi,
                            __nv_bfloat16* __restrict__ olo)
{
    __shared__ uint32_t Kph[64][9], Kpl[64][9];
    __shared__ uint32_t Vph[32][16], Vpl[32][16];
    int b = blockIdx.z, h = blockIdx.y;
    int q0 = blockIdx.x * 128;
    int t = threadIdx.x, lane = t & 31, w = t >> 5;
    int g = lane >> 2, tg = lane & 3;
    int qrow0 = q0 + w * 16 + g;
    int qrow1 = qrow0 + 8;

    uint32_t aqh[4], aql[4];
    {
        const float* q0p = qkv + ((size_t)(b * LL + qrow0)) * 1536 + h * 16;
        const float* q1p = qkv + ((size_t)(b * LL + qrow1)) * 1536 + h * 16;
        splitpack(q0p[2*tg] * 0.25f,   q0p[2*tg+1] * 0.25f,   aqh[0], aql[0]);
        splitpack(q1p[2*tg] * 0.25f,   q1p[2*tg+1] * 0.25f,   aqh[1], aql[1]);
        splitpack(q0p[8+2*tg] * 0.25f, q0p[8+2*tg+1] * 0.25f, aqh[2], aql[2]);
        splitpack(q1p[8+2*tg] * 0.25f, q1p[8+2*tg+1] * 0.25f, aqh[3], aql[3]);
    }

    float m0 = -3.0e38f, m1 = -3.0e38f, l0 = 0.f, l1 = 0.f;
    float of[2][4];
#pragma unroll
    for (int n2 = 0; n2 < 2; n2++)
#pragma unroll
        for (int e = 0; e < 4; e++) of[n2][e] = 0.f;

    int skey = t >> 1, shalf = t & 1;
    int vu = t - 128, vkp = vu >> 2, vdg = vu & 3;

    for (int j0 = 0; j0 < LL; j0 += 64) {
        __syncthreads();
        if (t < 128) {
            const float* kr = qkv + ((size_t)(b * LL + j0 + skey)) * 1536 + 512 + h * 16 + shalf * 8;
            float4 x = *(const float4*)kr;
            float4 y = *(const float4*)(kr + 4);
            uint32_t hi, lo;
            splitpack(x.x, x.y, hi, lo); Kph[skey][shalf*4+0] = hi; Kpl[skey][shalf*4+0] = lo;
            splitpack(x.z, x.w, hi, lo); Kph[skey][shalf*4+1] = hi; Kpl[skey][shalf*4+1] = lo;
            splitpack(y.x, y.y, hi, lo); Kph[skey][shalf*4+2] = hi; Kpl[skey][shalf*4+2] = lo;
            splitpack(y.z, y.w, hi, lo); Kph[skey][shalf*4+3] = hi; Kpl[skey][shalf*4+3] = lo;
        } else {
            const float* vr0 = qkv + ((size_t)(b * LL + j0 + 2*vkp)) * 1536 + 1024 + h * 16 + vdg * 4;
            const float* vr1 = vr0 + 1536;
            float4 u = *(const float4*)vr0;
            float4 v = *(const float4*)vr1;
            uint32_t hi, lo;
            splitpack(u.x, v.x, hi, lo); Vph[vkp][vdg*4+0] = hi; Vpl[vkp][vdg*4+0] = lo;
            splitpack(u.y, v.y, hi, lo); Vph[vkp][vdg*4+1] = hi; Vpl[vkp][vdg*4+1] = lo;
            splitpack(u.z, v.z, hi, lo); Vph[vkp][vdg*4+2] = hi; Vpl[vkp][vdg*4+2] = lo;
            splitpack(u.w, v.w, hi, lo); Vph[vkp][vdg*4+3] = hi; Vpl[vkp][vdg*4+3] = lo;
        }
        __syncthreads();

        float sc[8][4];
#pragma unroll
        for (int nt = 0; nt < 8; nt++) {
            uint32_t bh0 = Kph[nt*8+g][tg],   bh1 = Kph[nt*8+g][4+tg];
            uint32_t bl0 = Kpl[nt*8+g][tg],   bl1 = Kpl[nt*8+g][4+tg];
            sc[nt][0] = sc[nt][1] = sc[nt][2] = sc[nt][3] = 0.f;
            mma_bf16(sc[nt], aqh[0], aqh[1], aqh[2], aqh[3], bh0, bh1);
            mma_bf16(sc[nt], aqh[0], aqh[1], aqh[2], aqh[3], bl0, bl1);
            mma_bf16(sc[nt], aql[0], aql[1], aql[2], aql[3], bh0, bh1);
        }

        float tm0 = -3.0e38f, tm1 = -3.0e38f;
#pragma unroll
        for (int nt = 0; nt < 8; nt++) {
            tm0 = fmaxf(tm0, fmaxf(sc[nt][0], sc[nt][1]));
            tm1 = fmaxf(tm1, fmaxf(sc[nt][2], sc[nt][3]));
        }
        tm0 = fmaxf(tm0, __shfl_xor_sync(0xffffffffu, tm0, 1));
        tm0 = fmaxf(tm0, __shfl_xor_sync(0xffffffffu, tm0, 2));
        tm1 = fmaxf(tm1, __shfl_xor_sync(0xffffffffu, tm1, 1));
        tm1 = fmaxf(tm1, __shfl_xor_sync(0xffffffffu, tm1, 2));
        float mn0 = fmaxf(m0, tm0), mn1 = fmaxf(m1, tm1);
        float al0 = __expf(m0 - mn0), al1 = __expf(m1 - mn1);
        m0 = mn0; m1 = mn1;
        l0 *= al0; l1 *= al1;
#pragma unroll
        for (int n2 = 0; n2 < 2; n2++) {
            of[n2][0] *= al0; of[n2][1] *= al0;
            of[n2][2] *= al1; of[n2][3] *= al1;
        }
        // P packed as bf16 (hi only) — l kept exact in fp32
        uint32_t PH0[8], PH1[8];
#pragma unroll
        for (int nt = 0; nt < 8; nt++) {
            float p0 = __expf(sc[nt][0] - m0), p1 = __expf(sc[nt][1] - m0);
            float p2 = __expf(sc[nt][2] - m1), p3 = __expf(sc[nt][3] - m1);
            l0 += p0 + p1; l1 += p2 + p3;
            PH0[nt] = pack2bf(p0, p1);
            PH1[nt] = pack2bf(p2, p3);
        }

        // O += P (Vhi + Vlo): 2-product PV
#pragma unroll
        for (int ks = 0; ks < 4; ks++) {
#pragma unroll
            for (int n2 = 0; n2 < 2; n2++) {
                uint32_t b0h = Vph[8*ks+tg][n2*8+g],   b1h = Vph[8*ks+4+tg][n2*8+g];
                uint32_t b0l = Vpl[8*ks+tg][n2*8+g],   b1l = Vpl[8*ks+4+tg][n2*8+g];
                mma_bf16(of[n2], PH0[2*ks], PH1[2*ks], PH0[2*ks+1], PH1[2*ks+1], b0h, b1h);
                mma_bf16(of[n2], PH0[2*ks], PH1[2*ks], PH0[2*ks+1], PH1[2*ks+1], b0l, b1l);
            }
        }
    }

    l0 += __shfl_xor_sync(0xffffffffu, l0, 1);
    l0 += __shfl_xor_sync(0xffffffffu, l0, 2);
    l1 += __shfl_xor_sync(0xffffffffu, l1, 1);
    l1 += __shfl_xor_sync(0xffffffffu, l1, 2);
    float inv0 = 1.f / l0, inv1 = 1.f / l1;
    size_t o0 = ((size_t)(b * LL + qrow0)) * DD + h * 16;
    size_t o1 = ((size_t)(b * LL + qrow1)) * DD + h * 16;
#pragma unroll
    for (int n2 = 0; n2 < 2; n2++) {
#pragma unroll
        for (int e = 0; e < 2; e++) {
            int col = n2 * 8 + 2 * tg + e;
            float v0 = of[n2][e] * inv0;
            __nv_bfloat16 h0 = __float2bfloat16(v0);
            ohi[o0 + col] = h0;
            olo[o0 + col] = __float2bfloat16(v0 - __bfloat162float(h0));
            float v1 = of[n2][2 + e] * inv1;
            __nv_bfloat16 h1v = __float2bfloat16(v1);
            ohi[o1 + col] = h1v;
            olo[o1 + col] = __float2bfloat16(v1 - __bfloat162float(h1v));
        }
    }
}

// ---------------- layernorm (warp/row), float4, optional residual/split -----------
__global__ void ln_kernel(const float* __restrict__ X, const float* __restrict__ Yadd,
                          const float* __restrict__ g, const float* __restrict__ bb,
                          float* __restrict__ out,
                          __nv_bfloat16* __restrict__ ohi, __nv_bfloat16* __restrict__ olo)
{
    int warp = (blockIdx.x * blockDim.x + threadIdx.x) >> 5;
    int lane = threadIdx.x & 31;
    if (warp >= ROWS) return;
    const float4* x4 = (const float4*)(X + (size_t)warp * DD);
    const float4* y4 = Yadd ? (const float4*)(Yadd + (size_t)warp * DD) : nullptr;
    float4 v[4];
    float sum = 0.f;
#pragma unroll
    for (int i = 0; i < 4; i++) {
        float4 tv = x4[lane + i * 32];
        if (y4) {
            float4 av = y4[lane + i * 32];
            tv.x += av.x; tv.y += av.y; tv.z += av.z; tv.w += av.w;
        }
        v[i] = tv;
        sum += (tv.x + tv.y) + (tv.z + tv.w);
    }
#pragma unroll
    for (int o = 16; o > 0; o >>= 1) sum += __shfl_xor_sync(0xffffffffu, sum, o);
    float mean = sum * (1.f / DD);
    float vs = 0.f;
#pragma unroll
    for (int i = 0; i < 4; i++) {
        float dx = v[i].x - mean, dy = v[i].y - mean, dz = v[i].z - mean, dw = v[i].w - mean;
        vs += (dx*dx + dy*dy) + (dz*dz + dw*dw);
    }
#pragma unroll
    for (int o = 16; o > 0; o >>= 1) vs += __shfl_xor_sync(0xffffffffu, vs, o);
    float r = rsqrtf(vs * (1.f / DD) + EPSF);
    float4* op = (float4*)(out + (size_t)warp * DD);
    const float4* g4 = (const float4*)g;
    const float4* b4 = (const float4*)bb;
#pragma unroll
    for (int i = 0; i < 4; i++) {
        int c4 = lane + i * 32;
        float4 gv = g4[c4], bv = b4[c4];
        float4 ov;
        ov.x = (v[i].x - mean) * r * gv.x + bv.x;
        ov.y = (v[i].y - mean) * r * gv.y + bv.y;
        ov.z = (v[i].z - mean) * r * gv.z + bv.z;
        ov.w = (v[i].w - mean) * r * gv.w + bv.w;
        op[c4] = ov;
        if (ohi) {
            uint32_t ha, la, hb, lb;
            splitpack(ov.x, ov.y, ha, la);
            splitpack(ov.z, ov.w, hb, lb);
            ((uint2*)(ohi + (size_t)warp * DD))[c4] = make_uint2(ha, hb);
            ((uint2*)(olo + (size_t)warp * DD))[c4] = make_uint2(la, lb);
        }
    }
}

// ---------------- depthwise causal conv (K=4) + silu, 4 l/thread, both dirs -------
__global__ void conv_kernel(const float* __restrict__ zx0f, const float* __restrict__ cw0,
                            const float* __restrict__ cb0, float* __restrict__ xbc0f,
                            const float* __restrict__ zx1f, const float* __restrict__ cw1,
                            const float* __restrict__ cb1, float* __restrict__ xbc1f)
{
    int dir = blockIdx.y;
    const float* zx = dir ? zx1f : zx0f;
    const float* cw = dir ? cw1 : cw0;
    const float* cb = dir ? cb1 : cb0;
    float* xbc      = dir ? xbc1f : xbc0f;
    int tid = blockIdx.x * blockDim.x + threadIdx.x;
    if (tid >= (ROWS / 4) * CONVD) return;
    int c = tid % CONVD;
    int r4 = tid / CONVD;
    int bl0 = r4 * 4;
    int l0 = bl0 & 2047;
    const float* base = zx + (size_t)bl0 * DPROJ + DIN + c;
    float4 wv = *(const float4*)(cw + c * 4);
    float cbv = cb[c];
    float in[7];
#pragma unroll
    for (int j = 0; j < 7; j++) {
        int dl = j - 3;
        in[j] = (l0 + dl >= 0) ? base[dl * DPROJ] : 0.f;
    }
#pragma unroll
    for (int jo = 0; jo < 4; jo++) {
        float a = cbv;
        a = fmaf(in[jo],     wv.x, a);
        a = fmaf(in[jo + 1], wv.y, a);
        a = fmaf(in[jo + 2], wv.z, a);
        a = fmaf(in[jo + 3], wv.w, a);
        xbc[(size_t)(bl0 + jo) * CONVD + c] = a * (1.f / (1.f + __expf(-a)));
    }
}

// ---------------- dt / dA, both dirs ----------------------------------------------
__global__ void dtdA_kernel(const float* __restrict__ zx0f, const float* __restrict__ dtb0,
                            const float* __restrict__ Alog0,
                            float* __restrict__ dtf, float* __restrict__ dAf,
                            const float* __restrict__ zx1f, const float* __restrict__ dtb1,
                            const float* __restrict__ Alog1,
                            float* __restrict__ dtb_, float* __restrict__ dAb_)
{
    int dir = blockIdx.y;
    const float* zx  = dir ? zx1f : zx0f;
    const float* dtb = dir ? dtb1 : dtb0;
    const float* Alog= dir ? Alog1 : Alog0;
    float* dt = dir ? dtb_ : dtf;
    float* dA = dir ? dAb_ : dAf;
    int idx = blockIdx.x * blockDim.x + threadIdx.x;
    if (idx >= ROWS * NHM) return;
    int hm = idx & 15;
    int bl = idx >> 4;
    float raw = zx[(size_t)bl * DPROJ + (DPROJ - NHM) + hm] + dtb[hm];
    float dtv = (raw > 20.f) ? raw : log1pf(__expf(raw));
    float dAv = __expf(-__expf(Alog[hm]) * dtv);
    dt[idx] = dtv; dA[idx] = dAv;
}

// ---------------- sequential SSM scan: 2 steps per barrier, 4-buffer ring ---------
__global__ void scan_kernel(
    const float* __restrict__ xbc0, const float* __restrict__ dt0, const float* __restrict__ dA0,
    const float* __restrict__ Dp0, float* __restrict__ y0,
    const float* __restrict__ xbc1, const float* __restrict__ dt1, const float* __restrict__ dA1,
    const float* __restrict__ Dp1, float* __restrict__ y1)
{
    int z = blockIdx.z;
    int b = z & 1, dir = z >> 1;
    const float* xbc = dir ? xbc1 : xbc0;
    const float* dtp = dir ? dt1 : dt0;
    const float* dAp = dir ? dA1 : dA0;
    const float* Dp  = dir ? Dp1 : Dp0;
    float* y         = dir ? y1 : y0;
    int h = blockIdx.y, pc = blockIdx.x;
    int t = threadIdx.x;
    int p_local = t >> 1, nhalf = t & 1;

    __shared__ float sm[4][160];

    const float* src = nullptr;
    int stride = 0;
    if (t < 16)        { src = xbc + h * 64 + pc * 16 + t;      stride = CONVD; }
    else if (t < 80)   { src = xbc + DIN + (t - 16);            stride = CONVD; }
    else if (t < 144)  { src = xbc + DIN + NNc + (t - 80);      stride = CONVD; }
    else if (t == 144) { src = dtp + h;                         stride = NHM; }
    else if (t == 145) { src = dAp + h;                         stride = NHM; }

    size_t base_bl = (size_t)b * LL;
    if (src) src += base_bl * stride;

    float s[32];
#pragma unroll
    for (int k = 0; k < 32; k++) s[k] = 0.f;
    float dcoef = Dp[h];

    float r0 = 0.f, r1 = 0.f, r2 = 0.f, r3 = 0.f;
    if (src) {
        r0 = src[0];
        r1 = src[stride];
        r2 = src[2 * (size_t)stride];
        r3 = src[3 * (size_t)stride];
    }

    int pair = 0;
    for (int l = 0; l < LL; l += 2) {
        float* b0 = sm[2 * pair];
        float* b1 = sm[2 * pair + 1];
        if (t < 146) { b0[t] = r0; b1[t] = r1; }
        __syncthreads();
        r0 = r2; r1 = r3;
        if (src) {
            r2 = (l + 4 < LL) ? src[(size_t)(l + 4) * stride] : 0.f;
            r3 = (l + 5 < LL) ? src[(size_t)(l + 5) * stride] : 0.f;
        }
        if (t < 32) {
#pragma unroll
            for (int step = 0; step < 2; step++) {
                const float* bf = step ? b1 : b0;
                float dtv = bf[144];
                float dAv = bf[145];
                float xv  = bf[p_local];
                float cx  = dtv * xv;
                const float* Bb = bf + 16 + nhalf * 32;
                const float* Cb = bf + 80 + nhalf * 32;
                float pk[8];
#pragma unroll
                for (int k = 0; k < 8; k++) {
                    float4 Bv = *(const float4*)(Bb + 4 * k);
                    float4 Cv = *(const float4*)(Cb + 4 * k);
                    s[4*k+0] = fmaf(s[4*k+0], dAv, cx * Bv.x);
                    s[4*k+1] = fmaf(s[4*k+1], dAv, cx * Bv.y);
                    s[4*k+2] = fmaf(s[4*k+2], dAv, cx * Bv.z);
                    s[4*k+3] = fmaf(s[4*k+3], dAv, cx * Bv.w);
                    pk[k] = (s[4*k+0] * Cv.x + s[4*k+1] * Cv.y)
                          + (s[4*k+2] * Cv.z + s[4*k+3] * Cv.w);
                }
                float part = ((pk[0] + pk[1]) + (pk[2] + pk[3]))
                           + ((pk[4] + pk[5]) + (pk[6] + pk[7]));
                part += __shfl_xor_sync(0xffffffffu, part, 1);
                if (nhalf == 0)
                    y[(base_bl + l + step) * DIN + h * 64 + pc * 16 + p_local]
                        = part + dcoef * xv;
            }
        }
        pair ^= 1;
    }
}

// ---------------- gated RMSNorm, float4, fused bf16 split, both dirs --------------
__global__ void rmsgate_kernel(const float* __restrict__ y0f, const float* __restrict__ zx0f,
                               const float* __restrict__ nw0,
                               __nv_bfloat16* __restrict__ oh0, __nv_bfloat16* __restrict__ ol0,
                               const float* __restrict__ y1f, const float* __restrict__ zx1f,
                               const float* __restrict__ nw1,
                               __nv_bfloat16* __restrict__ oh1, __nv_bfloat16* __restrict__ ol1)
{
    int dir = blockIdx.y;
    const float* y  = dir ? y1f : y0f;
    const float* zx = dir ? zx1f : zx0f;
    const float* nw = dir ? nw1 : nw0;
    __nv_bfloat16* ohi = dir ? oh1 : oh0;
    __nv_bfloat16* olo = dir ? ol1 : ol0;
    int warp = (blockIdx.x * blockDim.x + threadIdx.x) >> 5;
    int lane = threadIdx.x & 31;
    if (warp >= ROWS) return;
    const float4* z4 = (const float4*)(zx + (size_t)warp * DPROJ);
    const float4* yr4 = (const float4*)(y + (size_t)warp * DIN);
    float4 v[8];
    float ss = 0.f;
#pragma unroll
    for (int i = 0; i < 8; i++) {
        int c4 = lane + i * 32;
        float4 zv = z4[c4];
        float4 yv = yr4[c4];
        yv.x *= zv.x * (1.f / (1.f + __expf(-zv.x)));
        yv.y *= zv.y * (1.f / (1.f + __expf(-zv.y)));
        yv.z *= zv.z * (1.f / (1.f + __expf(-zv.z)));
        yv.w *= zv.w * (1.f / (1.f + __expf(-zv.w)));
        v[i] = yv;
        ss += (yv.x*yv.x + yv.y*yv.y) + (yv.z*yv.z + yv.w*yv.w);
    }
#pragma unroll
    for (int o = 16; o > 0; o >>= 1) ss += __shfl_xor_sync(0xffffffffu, ss, o);
    float r = rsqrtf(ss * (1.f / DIN) + EPSF);
    const float4* nw4 = (const float4*)nw;
#pragma unroll
    for (int i = 0; i < 8; i++) {
        int c4 = lane + i * 32;
        float4 nv = nw4[c4];
        float a = v[i].x * r * nv.x, bq = v[i].y * r * nv.y;
        float cq = v[i].z * r * nv.z, d = v[i].w * r * nv.w;
        uint32_t ha, la, hb, lb;
        splitpack(a, bq, ha, la);
        splitpack(cq, d, hb, lb);
        ((uint2*)(ohi + (size_t)warp * DIN))[c4] = make_uint2(ha, hb);
        ((uint2*)(olo + (size_t)warp * DIN))[c4] = make_uint2(la, lb);
    }
}

// ---------------- launcher ---------------------------------------------------------
extern "C" void kernel_launch(void* const* d_in, const int* in_sizes, int n_in,
                              void* d_out, int out_size)
{
    const float* h      = (const float*)d_in[0];
    const float* Wqkv   = (const float*)d_in[1];
    const float* bqkv   = (const float*)d_in[2];
    const float* Wo_a   = (const float*)d_in[3];
    const float* bo_a   = (const float*)d_in[4];
    const float* g1     = (const float*)d_in[5];
    const float* b1     = (const float*)d_in[6];
    const float* g2     = (const float*)d_in[7];
    const float* b2     = (const float*)d_in[8];
    const float* f_Wi   = (const float*)d_in[9];
    const float* f_cw   = (const float*)d_in[10];
    const float* f_cb   = (const float*)d_in[11];
    const float* f_dtb  = (const float*)d_in[12];
    const float* f_Alog = (const float*)d_in[13];
    const float* f_D    = (const float*)d_in[14];
    const float* f_nw   = (const float*)d_in[15];
    const float* f_Wo   = (const float*)d_in[16];
    const float* bw_Wi  = (const float*)d_in[17];
    const float* bw_cw  = (const float*)d_in[18];
    const float* bw_cb  = (const float*)d_in[19];
    const float* bw_dtb = (const float*)d_in[20];
    const float* bw_Alog= (const float*)d_in[21];
    const float* bw_D   = (const float*)d_in[22];
    const float* bw_nw  = (const float*)d_in[23];
    const float* bw_Wo  = (const float*)d_in[24];
    float* out = (float*)d_out;

    cudaFuncSetAttribute(gemm_nt, cudaFuncAttributeMaxDynamicSharedMemorySize, GSMEM);

    float *qkvb, *aproj, *h1, *zx0, *zx1, *xbc0, *xbc1;
    float *dt0, *dt1, *dA0, *dA1, *y0, *y1, *acc, *acc2;
    cudaGetSymbolAddress((void**)&qkvb, g_qkv);
    cudaGetSymbolAddress((void**)&aproj, g_aproj);
    cudaGetSymbolAddress((void**)&h1, g_h1);
    cudaGetSymbolAddress((void**)&zx0, g_zx0);
    cudaGetSymbolAddress((void**)&zx1, g_zx1);
    cudaGetSymbolAddress((void**)&xbc0, g_xbc0);
    cudaGetSymbolAddress((void**)&xbc1, g_xbc1);
    cudaGetSymbolAddress((void**)&dt0, g_dt0);
    cudaGetSymbolAddress((void**)&dt1, g_dt1);
    cudaGetSymbolAddress((void**)&dA0, g_dA0);
    cudaGetSymbolAddress((void**)&dA1, g_dA1);
    cudaGetSymbolAddress((void**)&y0, g_y0);
    cudaGetSymbolAddress((void**)&y1, g_y1);
    cudaGetSymbolAddress((void**)&acc, g_acc);
    cudaGetSymbolAddress((void**)&acc2, g_acc2);

    __nv_bfloat16 *hH, *hL, *atH, *atL, *h1H, *h1L, *y0H, *y0L, *y1H, *y1L;
    __nv_bfloat16 *wqH, *wqL, *waH, *waL, *fiH, *fiL, *biH, *biL, *foH, *foL, *boH, *boL;
    cudaGetSymbolAddress((void**)&hH, g_h_hi);   cudaGetSymbolAddress((void**)&hL, g_h_lo);
    cudaGetSymbolAddress((void**)&atH, g_at_hi); cudaGetSymbolAddress((void**)&atL, g_at_lo);
    cudaGetSymbolAddress((void**)&h1H, g_h1_hi); cudaGetSymbolAddress((void**)&h1L, g_h1_lo);
    cudaGetSymbolAddress((void**)&y0H, g_y0_hi); cudaGetSymbolAddress((void**)&y0L, g_y0_lo);
    cudaGetSymbolAddress((void**)&y1H, g_y1_hi); cudaGetSymbolAddress((void**)&y1L, g_y1_lo);
    cudaGetSymbolAddress((void**)&wqH, g_wqkv_hi); cudaGetSymbolAddress((void**)&wqL, g_wqkv_lo);
    cudaGetSymbolAddress((void**)&waH, g_woa_hi);  cudaGetSymbolAddress((void**)&waL, g_woa_lo);
    cudaGetSymbolAddress((void**)&fiH, g_fwi_hi);  cudaGetSymbolAddress((void**)&fiL, g_fwi_lo);
    cudaGetSymbolAddress((void**)&biH, g_bwi_hi);  cudaGetSymbolAddress((void**)&biL, g_bwi_lo);
    cudaGetSymbolAddress((void**)&foH, g_fwo_hi);  cudaGetSymbolAddress((void**)&foL, g_fwo_lo);
    cudaGetSymbolAddress((void**)&boH, g_bwo_hi);  cudaGetSymbolAddress((void**)&boL, g_bwo_lo);

    // 0) one segmented float4 split for all weights + h
    split_all_kernel<<<(SP6 / 4 + 255) / 256, 256>>>(
        Wqkv, wqH, wqL,  Wo_a, waH, waL,  f_Wi, fiH, fiL,  bw_Wi, biH, biL,
        f_Wo, foH, foL,  bw_Wo, boH, boL,  h, hH, hL);

    // 1) qkv = h @ Wqkv^T + bqkv (single problem, z=1)
    gemm_nt<<<dim3(24, 32, 1), 256, GSMEM>>>(
        hH, hL, wqH, wqL, bqkv, nullptr, qkvb, 0, 0,
        hH, hL, wqH, wqL, bqkv, nullptr, qkvb, 0, 0,
        1536, 512);
    // 2) attention (bf16 mma, 128 q/block, P bf16)
    attn_kernel<<<dim3(16, 32, 2), 256>>>(qkvb, atH, atL);
    // 3) attn out-proj (single problem)
    gemm_nt<<<dim3(8, 32, 1), 256, GSMEM>>>(
        atH, atL, waH, waL, bo_a, nullptr, aproj, 0, 0,
        atH, atL, waH, waL, bo_a, nullptr, aproj, 0, 0,
        512, 512);
    // 4) h1 = LN(h + aproj), fused split
    ln_kernel<<<512, 256>>>(h, aproj, g1, b1, h1, h1H, h1L);
    // 5) mamba in-projections fwd+bwd merged (z=2)
    gemm_nt<<<dim3(35, 32, 2), 256, GSMEM>>>(
        h1H, h1L, fiH, fiL, nullptr, nullptr, zx0, 0, 0,
        h1H, h1L, biH, biL, nullptr, nullptr, zx1, 1, 0,
        DPROJ, 512);
    // 6) depthwise conv + silu (4 l/thread, both dirs)
    conv_kernel<<<dim3(((ROWS / 4) * CONVD + 255) / 256, 2), 256>>>(
        zx0, f_cw, f_cb, xbc0, zx1, bw_cw, bw_cb, xbc1);
    // 7) dt / dA (both dirs)
    dtdA_kernel<<<dim3(256, 2), 256>>>(zx0, f_dtb, f_Alog, dt0, dA0,
                                       zx1, bw_dtb, bw_Alog, dt1, dA1);
    // 8) SSM scan, both directions concurrently (2 steps/barrier)
    scan_kernel<<<dim3(4, 16, 4), 160>>>(xbc0, dt0, dA0, f_D, y0,
                                         xbc1, dt1, dA1, bw_D, y1);
    // 9) gated RMSNorm, fused split (both dirs)
    rmsgate_kernel<<<dim3(512, 2), 256>>>(y0, zx0, f_nw, y0H, y0L,
                                          y1, zx1, bw_nw, y1H, y1L);
    // 10) out-projections merged: z0: acc = h1 + yf@fWo^T ; z1: acc2 = rev(yb@bWo^T)
    gemm_nt<<<dim3(8, 32, 2), 256, GSMEM>>>(
        y0H, y0L, foH, foL, nullptr, h1, acc, 0, 0,
        y1H, y1L, boH, boL, nullptr, nullptr, acc2, 0, 1,
        512, 1024);
    // 11) final LN over (acc + acc2)
    ln_kernel<<<512, 256>>>(acc, acc2, g2, b2, out, nullptr, nullptr);
}